// round 5
// baseline (speedup 1.0000x reference)
#include <cuda_runtime.h>

#define D 64
#define L 64
#define BB 8
#define MAT (D*D)          // 4096 floats per matrix
#define NMAT (BB*L)        // 512 matrices
#define PA 68              // padded pitch for A tile (64 + 4)
#define PB 36              // padded pitch for B half-tile (32 + 4)

// All matrices in reciprocal-exp domain: W = exp(-m).
// log-semiring matmul:  out[i,j] = rcp( sum_k rcp( A[i,k] + B[k,j] ) )
__device__ float g_buf0[NMAT * MAT];   // 8MB
__device__ float g_buf1[NMAT * MAT];   // 8MB
__device__ float g_wtab[4 * MAT];      // exp(-p[a+1])
__device__ float g_ttab[16 * MAT];     // pair products  W(a) (x) W(b)
__device__ float g_qtab[256 * MAT];    // quad products  pair (x) pair
__device__ float g_p0tab[MAT];         // exp(-p[0])

__device__ __forceinline__ float frcp(float x) {
    float r;
    asm("rcp.approx.f32 %0, %1;" : "=f"(r) : "f"(x));
    return r;
}

// ---------------------------------------------------------------------------
// Half matmul: one CTA computes a 64x32 column slice (half h) of Dst = A (x) B.
// 256 threads; thread t owns rows {2*rg, 2*rg+1} x cols h*32 + cg*4 .. +3,
// where rg = t>>3 (0..31), cg = t&7 (0..7).
// ---------------------------------------------------------------------------
__device__ __forceinline__ void mm_half(const float* __restrict__ A,
                                        const float* __restrict__ B,
                                        float* __restrict__ Dst, int h) {
    __shared__ float sA[D * PA];       // full A (64x64), padded pitch
    __shared__ float sB[D * PB];       // half of B (64 k-rows x 32 cols), padded
    const int t = threadIdx.x;

    // stage A: 1024 float4 over 256 threads -> 4 each
#pragma unroll
    for (int i = 0; i < 4; i++) {
        int idx = t + i * 256;          // float4 index 0..1023
        int r = idx >> 4, c = idx & 15;
        *(float4*)&sA[r * PA + c * 4] = ((const float4*)A)[idx];
    }
    // stage B half: 512 float4 over 256 threads -> 2 each
#pragma unroll
    for (int i = 0; i < 2; i++) {
        int idx = t + i * 256;          // 0..511
        int k = idx >> 3, g = idx & 7;
        *(float4*)&sB[k * PB + g * 4] = *(const float4*)&B[k * D + h * 32 + g * 4];
    }
    __syncthreads();

    const int rg = t >> 3, cg = t & 7;
    const float* ap0 = &sA[(2 * rg + 0) * PA];
    const float* ap1 = &sA[(2 * rg + 1) * PA];
    const float* bp = &sB[cg * 4];
    float acc00 = 0.f, acc01 = 0.f, acc02 = 0.f, acc03 = 0.f;
    float acc10 = 0.f, acc11 = 0.f, acc12 = 0.f, acc13 = 0.f;

#pragma unroll 4
    for (int k4 = 0; k4 < 16; k4++) {
        float4 a0 = *(const float4*)&ap0[k4 * 4];
        float4 a1 = *(const float4*)&ap1[k4 * 4];
        float4 b0 = *(const float4*)&bp[(k4 * 4 + 0) * PB];
        float4 b1 = *(const float4*)&bp[(k4 * 4 + 1) * PB];
        float4 b2 = *(const float4*)&bp[(k4 * 4 + 2) * PB];
        float4 b3 = *(const float4*)&bp[(k4 * 4 + 3) * PB];

        acc00 += frcp(a0.x + b0.x); acc01 += frcp(a0.x + b0.y);
        acc02 += frcp(a0.x + b0.z); acc03 += frcp(a0.x + b0.w);
        acc10 += frcp(a1.x + b0.x); acc11 += frcp(a1.x + b0.y);
        acc12 += frcp(a1.x + b0.z); acc13 += frcp(a1.x + b0.w);

        acc00 += frcp(a0.y + b1.x); acc01 += frcp(a0.y + b1.y);
        acc02 += frcp(a0.y + b1.z); acc03 += frcp(a0.y + b1.w);
        acc10 += frcp(a1.y + b1.x); acc11 += frcp(a1.y + b1.y);
        acc12 += frcp(a1.y + b1.z); acc13 += frcp(a1.y + b1.w);

        acc00 += frcp(a0.z + b2.x); acc01 += frcp(a0.z + b2.y);
        acc02 += frcp(a0.z + b2.z); acc03 += frcp(a0.z + b2.w);
        acc10 += frcp(a1.z + b2.x); acc11 += frcp(a1.z + b2.y);
        acc12 += frcp(a1.z + b2.z); acc13 += frcp(a1.z + b2.w);

        acc00 += frcp(a0.w + b3.x); acc01 += frcp(a0.w + b3.y);
        acc02 += frcp(a0.w + b3.z); acc03 += frcp(a0.w + b3.w);
        acc10 += frcp(a1.w + b3.x); acc11 += frcp(a1.w + b3.y);
        acc12 += frcp(a1.w + b3.z); acc13 += frcp(a1.w + b3.w);
    }

    float* o0 = &Dst[(2 * rg + 0) * D + h * 32 + cg * 4];
    float* o1 = &Dst[(2 * rg + 1) * D + h * 32 + cg * 4];
    *(float4*)o0 = make_float4(frcp(acc00), frcp(acc01), frcp(acc02), frcp(acc03));
    *(float4*)o1 = make_float4(frcp(acc10), frcp(acc11), frcp(acc12), frcp(acc13));
}

// ---------------------------------------------------------------------------
// "Latest value" resolver: where does value of index m live before pass 2^slog?
// ---------------------------------------------------------------------------
__device__ __forceinline__ const float* latest(const int* __restrict__ act,
                                               int b, int m, int slog) {
    size_t off = (size_t)(b * L + m) * MAT;
    if (m < 2) return g_buf0 + off;
    int p = 31 - __clz(m);
    if (p > slog - 1) p = slog - 1;
    if (p == 1) {
        if (m == 2) return g_buf1 + off;
        const int* a = act + b * L + (m - 3);
        int idx = ((a[0] * 4 + a[1]) * 4 + a[2]) * 4 + a[3];
        return g_qtab + (size_t)idx * MAT;
    }
    return (p & 1) ? g_buf1 + off : g_buf0 + off;
}

// ---------------------------------------------------------------------------
// Kernels
// ---------------------------------------------------------------------------
__global__ void exp_tab_kernel(const float* __restrict__ p) {
    int a = blockIdx.x;
    const float4* src = (const float4*)(p + (size_t)a * MAT);
    float4* dst = (a == 0) ? (float4*)g_p0tab
                           : (float4*)(g_wtab + (size_t)(a - 1) * MAT);
    for (int i = threadIdx.x; i < MAT / 4; i += 256) {
        float4 v = src[i];
        dst[i] = make_float4(expf(-v.x), expf(-v.y), expf(-v.z), expf(-v.w));
    }
}

// 16 pair products, 2 halves each = 32 CTAs
__global__ void __launch_bounds__(256, 5) pair_kernel() {
    int pidx = blockIdx.x >> 1, h = blockIdx.x & 1;
    int a = pidx >> 2, b = pidx & 3;
    mm_half(g_wtab + (size_t)a * MAT, g_wtab + (size_t)b * MAT,
            g_ttab + (size_t)pidx * MAT, h);
}

// quads (512) + tris (16) + step-1 copies for l=0,1 (16) = 544 CTAs
__global__ void __launch_bounds__(256, 5) stage2_kernel(const int* __restrict__ act) {
    int bid = blockIdx.x;
    if (bid < 512) {
        int qidx = bid >> 1, h = bid & 1;
        mm_half(g_ttab + (size_t)(qidx >> 4) * MAT,
                g_ttab + (size_t)(qidx & 15) * MAT,
                g_qtab + (size_t)qidx * MAT, h);
    } else if (bid < 528) {
        int i = bid - 512;
        int b = i >> 1, h = i & 1;
        int a0 = act[b * L], a12 = act[b * L + 1] * 4 + act[b * L + 2];
        mm_half(g_wtab + (size_t)a0 * MAT, g_ttab + (size_t)a12 * MAT,
                g_buf1 + (size_t)(b * L + 2) * MAT, h);
    } else {
        int i = bid - 528;                  // 0..15
        int b = i >> 1, which = i & 1;      // l = 0 or 1
        const float* src = which
            ? g_ttab + (size_t)(act[b * L] * 4 + act[b * L + 1]) * MAT
            : g_wtab + (size_t)act[b * L] * MAT;
        float* dst = g_buf0 + (size_t)(b * L + which) * MAT;
        for (int j = threadIdx.x; j < MAT / 4; j += 256)
            ((float4*)dst)[j] = ((const float4*)src)[j];
    }
}

// Doubling pass for step = 2^slog (slog >= 2). No copies; writes only l >= step.
__global__ void __launch_bounds__(256, 5) step_kernel(const int* __restrict__ act,
                                                      int slog) {
    int step = 1 << slog;
    int n = L - step;
    int idx = blockIdx.x >> 1, h = blockIdx.x & 1;
    int b = idx / n;
    int l = step + (idx - b * n);
    const float* A = latest(act, b, l - step, slog);
    const float* Bm = latest(act, b, l, slog);
    float* dstbuf = (slog & 1) ? g_buf1 : g_buf0;
    mm_half(A, Bm, dstbuf + (size_t)(b * L + l) * MAT, h);
}

// Final: x = init (x) PM ; y = x (x) p0 ; output in log domain.
__global__ void final_kernel(const int* __restrict__ act,
                             const float* __restrict__ init_vec,
                             float* __restrict__ out) {
    int bl = blockIdx.x;
    int b = bl >> 6, l = bl & 63;
    const float* W = latest(act, b, l, 6);
    __shared__ float ci[D];
    __shared__ float xw[D];
    int t = threadIdx.x;                   // 64 threads
    ci[t] = expf(-init_vec[t]);
    __syncthreads();

    float s = 0.f;
#pragma unroll 8
    for (int k = 0; k < D; k++)
        s += frcp(ci[k] + W[k * D + t]);
    xw[t] = frcp(s);
    __syncthreads();

    float s2 = 0.f;
#pragma unroll 8
    for (int k = 0; k < D; k++)
        s2 += frcp(xw[k] + g_p0tab[k * D + t]);
    out[(size_t)bl * D + t] = logf(s2);
}

extern "C" void kernel_launch(void* const* d_in, const int* in_sizes, int n_in,
                              void* d_out, int out_size) {
    const float* p        = (const float*)d_in[0];  // (5, 64, 64)
    const float* init_vec = (const float*)d_in[1];  // (64,)
    const int*   act      = (const int*)d_in[2];    // (8, 64)
    float* out = (float*)d_out;                     // (8, 64, 64)

    exp_tab_kernel<<<5, 256>>>(p);
    pair_kernel<<<32, 256>>>();
    stage2_kernel<<<544, 256>>>(act);
    step_kernel<<<8 * (L - 4)  * 2, 256>>>(act, 2);   // 960 CTAs -> buf0
    step_kernel<<<8 * (L - 8)  * 2, 256>>>(act, 3);   // 896 CTAs -> buf1
    step_kernel<<<8 * (L - 16) * 2, 256>>>(act, 4);   // 768 CTAs -> buf0
    step_kernel<<<8 * (L - 32) * 2, 256>>>(act, 5);   // 512 CTAs -> buf1
    final_kernel<<<512, 64>>>(act, init_vec, out);
}

// round 6
// speedup vs baseline: 1.0934x; 1.0934x over previous
#include <cuda_runtime.h>

#define D 64
#define L 64
#define BB 8
#define MAT (D*D)          // 4096 floats per matrix
#define NMAT (BB*L)        // 512 matrices
#define PA 68              // padded smem pitch for A (kills 8-way bank conflict)

// All matrices in reciprocal-exp domain: W = exp(-m).
// log-semiring matmul:  out[i,j] = rcp( sum_k rcp( A[i,k] + B[k,j] ) )
__device__ float g_buf0[NMAT * MAT];   // 8MB
__device__ float g_buf1[NMAT * MAT];   // 8MB
__device__ float g_wtab[4 * MAT];      // exp(-p[a+1])
__device__ float g_ttab[16 * MAT];     // pair products  W(a) (x) W(b)
__device__ float g_qtab[256 * MAT];    // quad products  pair (x) pair
__device__ float g_p0tab[MAT];         // exp(-p[0])

__device__ __forceinline__ float frcp(float x) {
    float r;
    asm("rcp.approx.f32 %0, %1;" : "=f"(r) : "f"(x));
    return r;
}

// ---------------------------------------------------------------------------
// Quarter matmul: one CTA computes a 64x16 column slice (quarter q) of
// Dst = A (x) B.   256 threads, thread = (row, colgroup of 4).
// ---------------------------------------------------------------------------
__device__ __forceinline__ void mm_quarter(const float* __restrict__ A,
                                           const float* __restrict__ B,
                                           float* __restrict__ Dst, int q) {
    __shared__ float sA[D * PA];       // full A, padded pitch
    __shared__ float sB[D * 16];       // quarter of B
    const int t = threadIdx.x;

    // stage A (4 float4 per thread)
#pragma unroll
    for (int i = 0; i < 4; i++) {
        int idx = t + i * 256;          // float4 index 0..1023
        int r = idx >> 4, c = idx & 15;
        *(float4*)&sA[r * PA + c * 4] = ((const float4*)A)[idx];
    }
    // stage B quarter (1 float4 per thread)
    {
        int k = t >> 2, g = t & 3;
        *(float4*)&sB[k * 16 + g * 4] = *(const float4*)&B[k * D + q * 16 + g * 4];
    }
    __syncthreads();

    const int row = t >> 2, cg = t & 3;
    const float* ap = &sA[row * PA];
    const float* bp = &sB[cg * 4];
    float a0 = 0.f, a1 = 0.f, a2 = 0.f, a3 = 0.f;
#pragma unroll
    for (int k4 = 0; k4 < 16; k4++) {
        float4 av = *(const float4*)&ap[k4 * 4];
        float4 bA = *(const float4*)&bp[(k4 * 4 + 0) * 16];
        float4 bB = *(const float4*)&bp[(k4 * 4 + 1) * 16];
        float4 bC = *(const float4*)&bp[(k4 * 4 + 2) * 16];
        float4 bD = *(const float4*)&bp[(k4 * 4 + 3) * 16];
        a0 += frcp(av.x + bA.x); a1 += frcp(av.x + bA.y);
        a2 += frcp(av.x + bA.z); a3 += frcp(av.x + bA.w);
        a0 += frcp(av.y + bB.x); a1 += frcp(av.y + bB.y);
        a2 += frcp(av.y + bB.z); a3 += frcp(av.y + bB.w);
        a0 += frcp(av.z + bC.x); a1 += frcp(av.z + bC.y);
        a2 += frcp(av.z + bC.z); a3 += frcp(av.z + bC.w);
        a0 += frcp(av.w + bD.x); a1 += frcp(av.w + bD.y);
        a2 += frcp(av.w + bD.z); a3 += frcp(av.w + bD.w);
    }
    *(float4*)&Dst[row * D + q * 16 + cg * 4] =
        make_float4(frcp(a0), frcp(a1), frcp(a2), frcp(a3));
}

// ---------------------------------------------------------------------------
// Eighth matmul: one CTA computes a 64x8 column slice (eighth e) of
// Dst = A (x) B.   256 threads, thread = (row, colpair of 2).
// Used for the small late passes to halve the tail quantum.
// ---------------------------------------------------------------------------
__device__ __forceinline__ void mm_eighth(const float* __restrict__ A,
                                          const float* __restrict__ B,
                                          float* __restrict__ Dst, int e) {
    __shared__ float sA[D * PA];       // full A, padded pitch
    __shared__ float sB[D * 8];        // eighth of B (64 k-rows x 8 cols)
    const int t = threadIdx.x;

    // stage A (4 float4 per thread)
#pragma unroll
    for (int i = 0; i < 4; i++) {
        int idx = t + i * 256;
        int r = idx >> 4, c = idx & 15;
        *(float4*)&sA[r * PA + c * 4] = ((const float4*)A)[idx];
    }
    // stage B eighth: 128 float4 (threads 0..127)
    if (t < 128) {
        int k = t >> 1, g = t & 1;
        *(float4*)&sB[k * 8 + g * 4] = *(const float4*)&B[k * D + e * 8 + g * 4];
    }
    __syncthreads();

    const int row = t >> 2, c2 = (t & 3) << 1;
    const float* ap = &sA[row * PA];
    const float* bp = &sB[c2];
    float a0 = 0.f, a1 = 0.f;
#pragma unroll
    for (int k4 = 0; k4 < 16; k4++) {
        float4 av = *(const float4*)&ap[k4 * 4];
        float2 b0 = *(const float2*)&bp[(k4 * 4 + 0) * 8];
        float2 b1 = *(const float2*)&bp[(k4 * 4 + 1) * 8];
        float2 b2 = *(const float2*)&bp[(k4 * 4 + 2) * 8];
        float2 b3 = *(const float2*)&bp[(k4 * 4 + 3) * 8];
        a0 += frcp(av.x + b0.x); a1 += frcp(av.x + b0.y);
        a0 += frcp(av.y + b1.x); a1 += frcp(av.y + b1.y);
        a0 += frcp(av.z + b2.x); a1 += frcp(av.z + b2.y);
        a0 += frcp(av.w + b3.x); a1 += frcp(av.w + b3.y);
    }
    *(float2*)&Dst[row * D + e * 8 + c2] = make_float2(frcp(a0), frcp(a1));
}

// ---------------------------------------------------------------------------
// "Latest value" resolver: where does value of index m live before pass 2^slog?
// ---------------------------------------------------------------------------
__device__ __forceinline__ const float* latest(const int* __restrict__ act,
                                               int b, int m, int slog) {
    size_t off = (size_t)(b * L + m) * MAT;
    if (m < 2) return g_buf0 + off;
    int p = 31 - __clz(m);
    if (p > slog - 1) p = slog - 1;
    if (p == 1) {
        if (m == 2) return g_buf1 + off;
        const int* a = act + b * L + (m - 3);
        int idx = ((a[0] * 4 + a[1]) * 4 + a[2]) * 4 + a[3];
        return g_qtab + (size_t)idx * MAT;
    }
    return (p & 1) ? g_buf1 + off : g_buf0 + off;
}

// ---------------------------------------------------------------------------
// Kernels
// ---------------------------------------------------------------------------
__global__ void exp_tab_kernel(const float* __restrict__ p) {
    int a = blockIdx.x;
    const float4* src = (const float4*)(p + (size_t)a * MAT);
    float4* dst = (a == 0) ? (float4*)g_p0tab
                           : (float4*)(g_wtab + (size_t)(a - 1) * MAT);
    for (int i = threadIdx.x; i < MAT / 4; i += 256) {
        float4 v = src[i];
        dst[i] = make_float4(expf(-v.x), expf(-v.y), expf(-v.z), expf(-v.w));
    }
}

// 16 pair products, 4 quarters each = 64 CTAs
__global__ void __launch_bounds__(256, 6) pair_kernel() {
    int pidx = blockIdx.x >> 2, q = blockIdx.x & 3;
    int a = pidx >> 2, b = pidx & 3;
    mm_quarter(g_wtab + (size_t)a * MAT, g_wtab + (size_t)b * MAT,
               g_ttab + (size_t)pidx * MAT, q);
}

// quads (1024) + tris (32) + step-1 copies for l=0,1 (16) = 1072 CTAs
__global__ void __launch_bounds__(256, 6) stage2_kernel(const int* __restrict__ act) {
    int bid = blockIdx.x;
    if (bid < 1024) {
        int qidx = bid >> 2, q = bid & 3;
        mm_quarter(g_ttab + (size_t)(qidx >> 4) * MAT,
                   g_ttab + (size_t)(qidx & 15) * MAT,
                   g_qtab + (size_t)qidx * MAT, q);
    } else if (bid < 1056) {
        int i = bid - 1024;
        int b = i >> 2, q = i & 3;
        int a0 = act[b * L], a12 = act[b * L + 1] * 4 + act[b * L + 2];
        mm_quarter(g_wtab + (size_t)a0 * MAT, g_ttab + (size_t)a12 * MAT,
                   g_buf1 + (size_t)(b * L + 2) * MAT, q);
    } else {
        int i = bid - 1056;                 // 0..15
        int b = i >> 1, which = i & 1;      // l = 0 or 1
        const float* src = which
            ? g_ttab + (size_t)(act[b * L] * 4 + act[b * L + 1]) * MAT
            : g_wtab + (size_t)act[b * L] * MAT;
        float* dst = g_buf0 + (size_t)(b * L + which) * MAT;
        for (int j = threadIdx.x; j < MAT / 4; j += 256)
            ((float4*)dst)[j] = ((const float4*)src)[j];
    }
}

// Doubling pass (quarter tiles) for step = 2^slog. Writes only l >= step.
__global__ void __launch_bounds__(256, 6) step_kernel(const int* __restrict__ act,
                                                      int slog) {
    int step = 1 << slog;
    int n = L - step;
    int idx = blockIdx.x >> 2, q = blockIdx.x & 3;
    int b = idx / n;
    int l = step + (idx - b * n);
    const float* A = latest(act, b, l - step, slog);
    const float* Bm = latest(act, b, l, slog);
    float* dstbuf = (slog & 1) ? g_buf1 : g_buf0;
    mm_quarter(A, Bm, dstbuf + (size_t)(b * L + l) * MAT, q);
}

// Doubling pass (eighth tiles) — for the small late passes.
__global__ void __launch_bounds__(256, 6) step_kernel8(const int* __restrict__ act,
                                                       int slog) {
    int step = 1 << slog;
    int n = L - step;
    int idx = blockIdx.x >> 3, e = blockIdx.x & 7;
    int b = idx / n;
    int l = step + (idx - b * n);
    const float* A = latest(act, b, l - step, slog);
    const float* Bm = latest(act, b, l, slog);
    float* dstbuf = (slog & 1) ? g_buf1 : g_buf0;
    mm_eighth(A, Bm, dstbuf + (size_t)(b * L + l) * MAT, e);
}

// Final: x = init (x) PM ; y = x (x) p0 ; output in log domain.
__global__ void final_kernel(const int* __restrict__ act,
                             const float* __restrict__ init_vec,
                             float* __restrict__ out) {
    int bl = blockIdx.x;
    int b = bl >> 6, l = bl & 63;
    const float* W = latest(act, b, l, 6);
    __shared__ float ci[D];
    __shared__ float xw[D];
    int t = threadIdx.x;                   // 64 threads
    ci[t] = expf(-init_vec[t]);
    __syncthreads();

    float s = 0.f;
#pragma unroll 8
    for (int k = 0; k < D; k++)
        s += frcp(ci[k] + W[k * D + t]);
    xw[t] = frcp(s);
    __syncthreads();

    float s2 = 0.f;
#pragma unroll 8
    for (int k = 0; k < D; k++)
        s2 += frcp(xw[k] + g_p0tab[k * D + t]);
    out[(size_t)bl * D + t] = logf(s2);
}

extern "C" void kernel_launch(void* const* d_in, const int* in_sizes, int n_in,
                              void* d_out, int out_size) {
    const float* p        = (const float*)d_in[0];  // (5, 64, 64)
    const float* init_vec = (const float*)d_in[1];  // (64,)
    const int*   act      = (const int*)d_in[2];    // (8, 64)
    float* out = (float*)d_out;                     // (8, 64, 64)

    exp_tab_kernel<<<5, 256>>>(p);
    pair_kernel<<<64, 256>>>();
    stage2_kernel<<<1072, 256>>>(act);
    step_kernel<<<8 * (L - 4)  * 4, 256>>>(act, 2);    // 1920 CTAs -> buf0
    step_kernel<<<8 * (L - 8)  * 4, 256>>>(act, 3);    // 1792 CTAs -> buf1
    step_kernel8<<<8 * (L - 16) * 8, 256>>>(act, 4);   // 3072 CTAs -> buf0
    step_kernel8<<<8 * (L - 32) * 8, 256>>>(act, 5);   // 2048 CTAs -> buf1
    final_kernel<<<512, 64>>>(act, init_vec, out);
}